// round 5
// baseline (speedup 1.0000x reference)
#include <cuda_runtime.h>
#include <cuda_bf16.h>
#include <stdint.h>

#define NSUP   1280
#define NQRY   65536
#define DIN    2048
#define DEMB   1024
#define NCLS   64
#define NSTEPS 5

// ---------------- scratch (device globals; no allocation) ----------------
__device__ __align__(256) __nv_bfloat16 g_Wt[(size_t)DEMB * DIN];      // [DEMB][DIN]
__device__ __align__(256) __nv_bfloat16 g_qx[(size_t)NQRY * DIN];
__device__ __align__(256) __nv_bfloat16 g_sx[(size_t)NSUP * DIN];
__device__ __align__(256) __nv_bfloat16 g_qemb[(size_t)NQRY * DEMB];
__device__ __align__(256) __nv_bfloat16 g_semb[(size_t)NSUP * DEMB];
__device__ float g_qnorm[NQRY];
__device__ float g_ssum[NCLS * DEMB];
__device__ float g_scount[NCLS];
__device__ float g_qsum[NCLS * DEMB];
__device__ float g_qcount[NCLS];
__device__ __align__(256) __nv_bfloat16 g_pb[NCLS * DEMB];             // prototypes bf16
__device__ float g_pnorm[NCLS];
__device__ int   g_labels[NQRY];

// ---------------- small utility kernels ----------------
__global__ void k_zero(float* __restrict__ p, int n) {
    int i = blockIdx.x * blockDim.x + threadIdx.x;
    if (i < n) p[i] = 0.f;
}

__global__ void k_convert(const float* __restrict__ x, __nv_bfloat16* __restrict__ y, int n4) {
    int i = blockIdx.x * blockDim.x + threadIdx.x;
    if (i < n4) {
        float4 v = ((const float4*)x)[i];
        ((__nv_bfloat162*)y)[2 * i + 0] = __floats2bfloat162_rn(v.x, v.y);
        ((__nv_bfloat162*)y)[2 * i + 1] = __floats2bfloat162_rn(v.z, v.w);
    }
}

// tiled transpose: W [DIN][DEMB] f32 -> Wt [DEMB][DIN] bf16
__global__ void k_transpose_w(const float* __restrict__ W, __nv_bfloat16* __restrict__ Wt) {
    __shared__ float tile[32][33];
    int n0 = blockIdx.x * 32, k0 = blockIdx.y * 32;
#pragma unroll
    for (int i = 0; i < 4; i++) {
        int k = k0 + threadIdx.y + i * 8;
        tile[threadIdx.y + i * 8][threadIdx.x] = W[(size_t)k * DEMB + n0 + threadIdx.x];
    }
    __syncthreads();
#pragma unroll
    for (int i = 0; i < 4; i++) {
        int n = n0 + threadIdx.y + i * 8;
        Wt[(size_t)n * DIN + k0 + threadIdx.x] =
            __float2bfloat16(tile[threadIdx.x][threadIdx.y + i * 8]);
    }
}

__global__ void k_supp_stats(const __nv_bfloat16* __restrict__ semb, const int* __restrict__ lab,
                             float* __restrict__ ssum, float* __restrict__ scount) {
    int r = blockIdx.x;
    int L = lab[r];
    if (threadIdx.x == 0) atomicAdd(&scount[L], 1.0f);
    for (int c = threadIdx.x; c < DEMB; c += blockDim.x)
        atomicAdd(&ssum[L * DEMB + c], __bfloat162float(semb[(size_t)r * DEMB + c]));
}

// prototypes from (ssum [+ qsum]) / counts; ALSO zeroes qsum/qcount for the next pass.
__global__ void k_proto(const float* __restrict__ ssum, const float* __restrict__ scount,
                        float* __restrict__ qsum, float* __restrict__ qcount,
                        int useq, __nv_bfloat16* __restrict__ pb, float* __restrict__ pnorm) {
    int c = blockIdx.x;
    float cnt = scount[c] + (useq ? qcount[c] : 0.f);
    float inv = 1.f / fmaxf(cnt, 1.f);
    float s = 0.f;
    for (int j = threadIdx.x; j < DEMB; j += blockDim.x) {
        float p = (ssum[c * DEMB + j] + (useq ? qsum[c * DEMB + j] : 0.f)) * inv;
        qsum[c * DEMB + j] = 0.f;  // ready for next segsum
        __nv_bfloat16 pv = __float2bfloat16(p);
        pb[c * DEMB + j] = pv;
        float pf = __bfloat162float(pv);
        s += pf * pf;
    }
    if (threadIdx.x == 0) qcount[c] = 0.f;
    __shared__ float red[8];
#pragma unroll
    for (int o2 = 16; o2; o2 >>= 1) s += __shfl_xor_sync(~0u, s, o2);
    if ((threadIdx.x & 31) == 0) red[threadIdx.x >> 5] = s;
    __syncthreads();
    if (threadIdx.x < 8) {
        s = red[threadIdx.x];
#pragma unroll
        for (int o2 = 4; o2; o2 >>= 1) s += __shfl_xor_sync(0xff, s, o2);
        if (threadIdx.x == 0) pnorm[c] = s;
    }
}

// segment-sum of query embeddings by label. bfloat162 loads, 2-row unroll into
// two independent smem accumulator banks. grid (DEMB/256, 32), 128 thr, 128KB smem.
__global__ void __launch_bounds__(128) k_segsum2(const __nv_bfloat16* __restrict__ qemb,
                                                 const int* __restrict__ lab,
                                                 float* __restrict__ qsum) {
    extern __shared__ float sacc[];  // 2 banks * NCLS * 256 floats = 128KB
    const int tid = threadIdx.x;
    for (int i = tid; i < 2 * NCLS * 256; i += 128) sacc[i] = 0.f;
    __syncthreads();
    float* a0 = sacc;
    float* a1 = sacc + NCLS * 256;
    const int colpair = blockIdx.x * 128 + tid;
    const __nv_bfloat162* q2 = (const __nv_bfloat162*)qemb;
    const int rpb = NQRY / gridDim.y;
    const int r0 = blockIdx.y * rpb;
    for (int r = r0; r < r0 + rpb; r += 2) {
        int L0 = __ldg(&lab[r]), L1 = __ldg(&lab[r + 1]);
        float2 v0 = __bfloat1622float2(q2[(size_t)r * 512 + colpair]);
        float2 v1 = __bfloat1622float2(q2[(size_t)(r + 1) * 512 + colpair]);
        float* p0 = &a0[L0 * 256 + tid * 2];
        p0[0] += v0.x; p0[1] += v0.y;
        float* p1 = &a1[L1 * 256 + tid * 2];
        p1[0] += v1.x; p1[1] += v1.y;
    }
    __syncthreads();
    for (int i = tid; i < NCLS * 256; i += 128) {
        int cls = i >> 8, cidx = i & 255;
        atomicAdd(&qsum[cls * DEMB + blockIdx.x * 256 + cidx], a0[i] + a1[i]);
    }
}

// ---------------- bf16 HMMA GEMM (mma.sync m16n8k16), swizzled smem ----------------
// C[M,N] = A[M,K] @ B[N,K]^T
// MODE 0: out_bf16 = C + bias[n]; if qnorm!=null also atomicAdd row sum-of-squares
// MODE 1: labels[m] = argmin_n (pnorm[n] - 2*C), qcount histogram
// MODE 2: outf[m*NCLS+n] = -sqrt(max(qnorm[m]+pnorm[n]-2*C, 1e-12))
// NS: pipeline stages (3: deep, 1 sync/iter; 2: lean smem, 2 syncs/iter)
#define CP_ASYNC(dst, src) asm volatile("cp.async.cg.shared.global [%0], [%1], 16;\n" ::"r"(dst), "l"(src))

template <int BM, int BN, int WMT, int WNT, int MODE, int NS, int MINB>
__global__ void __launch_bounds__(WMT* WNT * 32, MINB) k_gemm(
    const __nv_bfloat16* __restrict__ A, const __nv_bfloat16* __restrict__ B, int K,
    const float* __restrict__ bias, __nv_bfloat16* __restrict__ outb, int ldo,
    const float* __restrict__ pnorm, int* __restrict__ labels, float* __restrict__ qcount,
    float* __restrict__ qnorm, float* __restrict__ outf) {
    constexpr int NT = WMT * WNT * 32;
    constexpr int WM = BM / WMT, WN = BN / WNT;
    constexpr int MF = WM / 16, NF = WN / 8;
    constexpr int AIT = BM * 8 / NT;
    constexpr int BIT = BN * 8 / NT;
    constexpr uint32_t STAGE = (BM + BN) * 128;

    extern __shared__ char smem_raw[];
    uint32_t sbase = (uint32_t)__cvta_generic_to_shared(smem_raw);

    const int tid = threadIdx.x;
    const int warp = tid >> 5, lane = tid & 31;
    const int wm = (warp / WNT) * WM, wn = (warp % WNT) * WN;
    const int bm0 = blockIdx.y * BM, bn0 = blockIdx.x * BN;

    const __nv_bfloat16* Ab = A + (size_t)bm0 * K;
    const __nv_bfloat16* Bb = B + (size_t)bn0 * K;

    float acc[MF][NF][4];
#pragma unroll
    for (int i = 0; i < MF; i++)
#pragma unroll
        for (int j = 0; j < NF; j++)
#pragma unroll
            for (int q = 0; q < 4; q++) acc[i][j][q] = 0.f;

    const int KT = K >> 6;  // BK=64

    auto load = [&](int kt) {
        uint32_t sA = sbase + (kt % NS) * STAGE;
        uint32_t sB = sA + (uint32_t)BM * 128u;
        const __nv_bfloat16* Ap = Ab + (size_t)kt * 64;
        const __nv_bfloat16* Bp = Bb + (size_t)kt * 64;
#pragma unroll
        for (int i = 0; i < AIT; i++) {
            int idx = tid + i * NT;
            int r = idx >> 3, c = idx & 7;
            CP_ASYNC(sA + (uint32_t)(r * 128 + ((c ^ (r & 7)) * 16)), Ap + (size_t)r * K + c * 8);
        }
#pragma unroll
        for (int i = 0; i < BIT; i++) {
            int idx = tid + i * NT;
            int r = idx >> 3, c = idx & 7;
            CP_ASYNC(sB + (uint32_t)(r * 128 + ((c ^ (r & 7)) * 16)), Bp + (size_t)r * K + c * 8);
        }
        asm volatile("cp.async.commit_group;\n");
    };

    load(0);
    load(1);
    for (int kt = 0; kt < KT; kt++) {
        if (kt < KT - 1)
            asm volatile("cp.async.wait_group 1;\n" ::: "memory");
        else
            asm volatile("cp.async.wait_group 0;\n" ::: "memory");
        __syncthreads();
        if (NS == 3 && kt + 2 < KT) load(kt + 2);  // writes stage (kt-1)%3: already drained
        uint32_t aBase = sbase + (kt % NS) * STAGE;
        uint32_t bBase = aBase + (uint32_t)BM * 128u;
#pragma unroll
        for (int ks = 0; ks < 4; ks++) {
            uint32_t af[MF][4];
#pragma unroll
            for (int mi = 0; mi < MF; mi++) {
                int row = wm + mi * 16 + (lane & 15);
                int ch = (ks * 2 + (lane >> 4)) ^ (row & 7);
                uint32_t adr = aBase + (uint32_t)(row * 128 + ch * 16);
                asm volatile("ldmatrix.sync.aligned.m8n8.x4.shared.b16 {%0,%1,%2,%3},[%4];"
                             : "=r"(af[mi][0]), "=r"(af[mi][1]), "=r"(af[mi][2]), "=r"(af[mi][3])
                             : "r"(adr));
            }
            uint32_t bfr[NF][2];
#pragma unroll
            for (int ni2 = 0; ni2 < NF / 2; ni2++) {
                int nrow = wn + ni2 * 16 + (lane & 7) + ((lane >> 4) << 3);
                int ch = (ks * 2 + ((lane >> 3) & 1)) ^ (nrow & 7);
                uint32_t bd = bBase + (uint32_t)(nrow * 128 + ch * 16);
                uint32_t r0, r1, r2, r3;
                asm volatile("ldmatrix.sync.aligned.m8n8.x4.shared.b16 {%0,%1,%2,%3},[%4];"
                             : "=r"(r0), "=r"(r1), "=r"(r2), "=r"(r3)
                             : "r"(bd));
                bfr[2 * ni2][0] = r0; bfr[2 * ni2][1] = r1;
                bfr[2 * ni2 + 1][0] = r2; bfr[2 * ni2 + 1][1] = r3;
            }
#pragma unroll
            for (int mi = 0; mi < MF; mi++)
#pragma unroll
                for (int ni = 0; ni < NF; ni++)
                    asm volatile(
                        "mma.sync.aligned.m16n8k16.row.col.f32.bf16.bf16.f32 "
                        "{%0,%1,%2,%3},{%4,%5,%6,%7},{%8,%9},{%0,%1,%2,%3};"
                        : "+f"(acc[mi][ni][0]), "+f"(acc[mi][ni][1]),
                          "+f"(acc[mi][ni][2]), "+f"(acc[mi][ni][3])
                        : "r"(af[mi][0]), "r"(af[mi][1]), "r"(af[mi][2]), "r"(af[mi][3]),
                          "r"(bfr[ni][0]), "r"(bfr[ni][1]));
        }
        if (NS == 2) {
            __syncthreads();
            if (kt + 2 < KT) load(kt + 2);
        }
    }

    if (MODE == 0) {
#pragma unroll
        for (int mi = 0; mi < MF; mi++) {
            int row = bm0 + wm + mi * 16 + (lane >> 2);
#pragma unroll
            for (int h = 0; h < 2; h++) {
                int rr = row + h * 8;
                float rs = 0.f;
#pragma unroll
                for (int ni = 0; ni < NF; ni++) {
                    int col = bn0 + wn + ni * 8 + (lane & 3) * 2;
                    float b0v = __ldg(&bias[col]), b1v = __ldg(&bias[col + 1]);
                    __nv_bfloat162 p = __floats2bfloat162_rn(acc[mi][ni][2 * h] + b0v,
                                                             acc[mi][ni][2 * h + 1] + b1v);
                    *(__nv_bfloat162*)(outb + (size_t)rr * ldo + col) = p;
                    if (qnorm) {
                        float x = __bfloat162float(p.x), y = __bfloat162float(p.y);
                        rs += x * x + y * y;
                    }
                }
                if (qnorm) {
                    rs += __shfl_xor_sync(~0u, rs, 1);
                    rs += __shfl_xor_sync(~0u, rs, 2);
                    if ((lane & 3) == 0) atomicAdd(&qnorm[rr], rs);
                }
            }
        }
    } else if (MODE == 1) {
        float bv[MF][2];
        int bc[MF][2];
#pragma unroll
        for (int mi = 0; mi < MF; mi++)
#pragma unroll
            for (int h = 0; h < 2; h++) { bv[mi][h] = 1e30f; bc[mi][h] = 0; }
#pragma unroll
        for (int mi = 0; mi < MF; mi++)
#pragma unroll
            for (int ni = 0; ni < NF; ni++)
#pragma unroll
                for (int h = 0; h < 2; h++)
#pragma unroll
                    for (int j = 0; j < 2; j++) {
                        int c = wn + ni * 8 + (lane & 3) * 2 + j;
                        float m = pnorm[c] - 2.f * acc[mi][ni][2 * h + j];
                        if (m < bv[mi][h]) { bv[mi][h] = m; bc[mi][h] = c; }
                    }
#pragma unroll
        for (int off = 1; off <= 2; off <<= 1)
#pragma unroll
            for (int mi = 0; mi < MF; mi++)
#pragma unroll
                for (int h = 0; h < 2; h++) {
                    float ov = __shfl_xor_sync(~0u, bv[mi][h], off);
                    int oc = __shfl_xor_sync(~0u, bc[mi][h], off);
                    if (ov < bv[mi][h] || (ov == bv[mi][h] && oc < bc[mi][h])) {
                        bv[mi][h] = ov; bc[mi][h] = oc;
                    }
                }
        __syncthreads();
        float* redv = (float*)smem_raw;
        int* redi = (int*)smem_raw + BM * WNT;
        __shared__ int hist[NCLS];
        if (tid < NCLS) hist[tid] = 0;
        if ((lane & 3) == 0) {
#pragma unroll
            for (int mi = 0; mi < MF; mi++)
#pragma unroll
                for (int h = 0; h < 2; h++) {
                    int r = wm + mi * 16 + (lane >> 2) + 8 * h;
                    redv[r * WNT + (warp % WNT)] = bv[mi][h];
                    redi[r * WNT + (warp % WNT)] = bc[mi][h];
                }
        }
        __syncthreads();
        if (tid < BM) {
            float v = redv[tid * WNT];
            int cbest = redi[tid * WNT];
#pragma unroll
            for (int w2 = 1; w2 < WNT; w2++) {
                float ov = redv[tid * WNT + w2];
                int oc = redi[tid * WNT + w2];
                if (ov < v || (ov == v && oc < cbest)) { v = ov; cbest = oc; }
            }
            labels[bm0 + tid] = cbest;
            atomicAdd(&hist[cbest], 1);
        }
        __syncthreads();
        if (tid < NCLS) atomicAdd(&qcount[tid], (float)hist[tid]);
    } else {  // MODE 2
#pragma unroll
        for (int mi = 0; mi < MF; mi++) {
            int row = bm0 + wm + mi * 16 + (lane >> 2);
#pragma unroll
            for (int h = 0; h < 2; h++) {
                int rr = row + 8 * h;
                float qn = __ldg(&qnorm[rr]);
#pragma unroll
                for (int ni = 0; ni < NF; ni++)
#pragma unroll
                    for (int j = 0; j < 2; j++) {
                        int c = wn + ni * 8 + (lane & 3) * 2 + j;
                        float d2 = qn + pnorm[c] - 2.f * acc[mi][ni][2 * h + j];
                        outf[(size_t)rr * NCLS + c] = -sqrtf(fmaxf(d2, 1e-12f));
                    }
            }
        }
    }
}

// ---------------- host orchestration ----------------
extern "C" void kernel_launch(void* const* d_in, const int* in_sizes, int n_in,
                              void* d_out, int out_size) {
    (void)in_sizes; (void)n_in; (void)out_size;
    const float* support = (const float*)d_in[0];
    const float* query = (const float*)d_in[1];
    const int* slab = (const int*)d_in[2];
    const float* W = (const float*)d_in[3];
    const float* bias = (const float*)d_in[4];
    float* out = (float*)d_out;

    __nv_bfloat16 *Wt, *qx, *sx, *qemb, *semb, *pb;
    float *qnorm, *ssum, *scount, *qsum, *qcount, *pnorm;
    int* labels;
    cudaGetSymbolAddress((void**)&Wt, g_Wt);
    cudaGetSymbolAddress((void**)&qx, g_qx);
    cudaGetSymbolAddress((void**)&sx, g_sx);
    cudaGetSymbolAddress((void**)&qemb, g_qemb);
    cudaGetSymbolAddress((void**)&semb, g_semb);
    cudaGetSymbolAddress((void**)&qnorm, g_qnorm);
    cudaGetSymbolAddress((void**)&ssum, g_ssum);
    cudaGetSymbolAddress((void**)&scount, g_scount);
    cudaGetSymbolAddress((void**)&qsum, g_qsum);
    cudaGetSymbolAddress((void**)&qcount, g_qcount);
    cudaGetSymbolAddress((void**)&pb, g_pb);
    cudaGetSymbolAddress((void**)&pnorm, g_pnorm);
    cudaGetSymbolAddress((void**)&labels, g_labels);

    const int SMEM_BIG = 3 * (128 + 256) * 128;   // 147456
    const int SMEM_SML = 2 * (128 + 64) * 128;    // 49152 (2 stages -> 2 CTAs/SM)
    const int SMEM_SEG = 2 * NCLS * 256 * 4;      // 131072
    cudaFuncSetAttribute(k_gemm<128, 256, 2, 4, 0, 3, 1>, cudaFuncAttributeMaxDynamicSharedMemorySize, SMEM_BIG);
    cudaFuncSetAttribute(k_gemm<128, 64, 4, 2, 1, 2, 2>, cudaFuncAttributeMaxDynamicSharedMemorySize, SMEM_SML);
    cudaFuncSetAttribute(k_gemm<128, 64, 4, 2, 2, 2, 2>, cudaFuncAttributeMaxDynamicSharedMemorySize, SMEM_SML);
    cudaFuncSetAttribute(k_segsum2, cudaFuncAttributeMaxDynamicSharedMemorySize, SMEM_SEG);

    // conversions
    k_transpose_w<<<dim3(DEMB / 32, DIN / 32), dim3(32, 8)>>>(W, Wt);
    k_convert<<<(NSUP * DIN / 4 + 255) / 256, 256>>>(support, sx, NSUP * DIN / 4);
    k_convert<<<(NQRY * DIN / 4 + 255) / 256, 256>>>(query, qx, NQRY * DIN / 4);

    // embeddings (bf16 out, bias fused; query also accumulates qnorm)
    k_zero<<<(NQRY + 255) / 256, 256>>>(qnorm, NQRY);
    k_gemm<128, 256, 2, 4, 0, 3, 1><<<dim3(DEMB / 256, NSUP / 128), 256, SMEM_BIG>>>(
        sx, Wt, DIN, bias, semb, DEMB, nullptr, nullptr, nullptr, nullptr, nullptr);
    k_gemm<128, 256, 2, 4, 0, 3, 1><<<dim3(DEMB / 256, NQRY / 128), 256, SMEM_BIG>>>(
        qx, Wt, DIN, bias, qemb, DEMB, nullptr, nullptr, nullptr, qnorm, nullptr);

    // support class sums + counts -> initial prototypes (also zeroes qsum/qcount)
    k_zero<<<(NCLS * DEMB + 255) / 256, 256>>>(ssum, NCLS * DEMB);
    k_zero<<<1, 64>>>(scount, NCLS);
    k_supp_stats<<<NSUP, 256>>>(semb, slab, ssum, scount);
    k_proto<<<NCLS, 256>>>(ssum, scount, qsum, qcount, 0, pb, pnorm);

    for (int s = 0; s < NSTEPS; s++) {
        k_gemm<128, 64, 4, 2, 1, 2, 2><<<dim3(1, NQRY / 128), 256, SMEM_SML>>>(
            qemb, pb, DEMB, nullptr, nullptr, 0, pnorm, labels, qcount, nullptr, nullptr);
        k_segsum2<<<dim3(DEMB / 256, 32), 128, SMEM_SEG>>>(qemb, labels, qsum);
        k_proto<<<NCLS, 256>>>(ssum, scount, qsum, qcount, 1, pb, pnorm);
    }

    // final logits
    k_gemm<128, 64, 4, 2, 2, 2, 2><<<dim3(1, NQRY / 128), 256, SMEM_SML>>>(
        qemb, pb, DEMB, nullptr, nullptr, 0, pnorm, nullptr, nullptr, qnorm, out);
}

// round 6
// speedup vs baseline: 1.0309x; 1.0309x over previous
#include <cuda_runtime.h>
#include <cuda_bf16.h>
#include <stdint.h>

#define NSUP   1280
#define NQRY   65536
#define DIN    2048
#define DEMB   1024
#define NCLS   64
#define NSTEPS 5
#define QYB    (NQRY / 128)   // 512 query y-blocks

// ---------------- scratch (device globals; no allocation) ----------------
__device__ __align__(256) __nv_bfloat16 g_Wt[(size_t)DEMB * DIN];      // [DEMB][DIN]
__device__ __align__(256) __nv_bfloat16 g_qx[(size_t)NQRY * DIN];
__device__ __align__(256) __nv_bfloat16 g_sx[(size_t)NSUP * DIN];
__device__ __align__(256) __nv_bfloat16 g_qemb[(size_t)NQRY * DEMB];
__device__ __align__(256) __nv_bfloat16 g_semb[(size_t)NSUP * DEMB];
__device__ float g_qnorm[NQRY];
__device__ float g_ssum[NCLS * DEMB];
__device__ float g_scount[NCLS];
__device__ float g_qsum[NCLS * DEMB];
__device__ float g_qcount[NCLS];
__device__ __align__(256) __nv_bfloat16 g_pb[NCLS * DEMB];             // prototypes bf16
__device__ float g_pnorm[NCLS];
__device__ int   g_labels[NQRY];

// ---------------- small utility kernels ----------------
__global__ void k_zero(float* __restrict__ p, int n) {
    int i = blockIdx.x * blockDim.x + threadIdx.x;
    if (i < n) p[i] = 0.f;
}

__global__ void k_convert(const float* __restrict__ x, __nv_bfloat16* __restrict__ y, int n4) {
    int i = blockIdx.x * blockDim.x + threadIdx.x;
    if (i < n4) {
        float4 v = ((const float4*)x)[i];
        ((__nv_bfloat162*)y)[2 * i + 0] = __floats2bfloat162_rn(v.x, v.y);
        ((__nv_bfloat162*)y)[2 * i + 1] = __floats2bfloat162_rn(v.z, v.w);
    }
}

// tiled transpose: W [DIN][DEMB] f32 -> Wt [DEMB][DIN] bf16. Also zeroes qnorm.
__global__ void k_transpose_w(const float* __restrict__ W, __nv_bfloat16* __restrict__ Wt,
                              float* __restrict__ qnorm) {
    __shared__ float tile[32][33];
    int n0 = blockIdx.x * 32, k0 = blockIdx.y * 32;
#pragma unroll
    for (int i = 0; i < 4; i++) {
        int k = k0 + threadIdx.y + i * 8;
        tile[threadIdx.y + i * 8][threadIdx.x] = W[(size_t)k * DEMB + n0 + threadIdx.x];
    }
    // side task: zero qnorm (grid = 32*64 = 2048 blocks of 256 threads; need 65536)
    int bid = blockIdx.y * gridDim.x + blockIdx.x;
    int qi = bid * 32 + (threadIdx.y * 32 + threadIdx.x) / 8;  // 32 per block
    if ((threadIdx.x & 7) == 0 && qi < NQRY) qnorm[qi] = 0.f;
    __syncthreads();
#pragma unroll
    for (int i = 0; i < 4; i++) {
        int n = n0 + threadIdx.y + i * 8;
        Wt[(size_t)n * DIN + k0 + threadIdx.x] =
            __float2bfloat16(tile[threadIdx.x][threadIdx.y + i * 8]);
    }
}

__global__ void k_supp_stats(const __nv_bfloat16* __restrict__ semb, const int* __restrict__ lab,
                             float* __restrict__ ssum, float* __restrict__ scount) {
    int r = blockIdx.x;
    int L = lab[r];
    if (threadIdx.x == 0) atomicAdd(&scount[L], 1.0f);
    for (int c = threadIdx.x; c < DEMB; c += blockDim.x)
        atomicAdd(&ssum[L * DEMB + c], __bfloat162float(semb[(size_t)r * DEMB + c]));
}

// prototypes from (ssum [+ qsum]) / counts; ALSO zeroes qsum/qcount for the next pass.
__global__ void k_proto(const float* __restrict__ ssum, const float* __restrict__ scount,
                        float* __restrict__ qsum, float* __restrict__ qcount,
                        int useq, __nv_bfloat16* __restrict__ pb, float* __restrict__ pnorm) {
    int c = blockIdx.x;
    float cnt = scount[c] + (useq ? qcount[c] : 0.f);
    float inv = 1.f / fmaxf(cnt, 1.f);
    float s = 0.f;
    for (int j = threadIdx.x; j < DEMB; j += blockDim.x) {
        float p = (ssum[c * DEMB + j] + (useq ? qsum[c * DEMB + j] : 0.f)) * inv;
        qsum[c * DEMB + j] = 0.f;
        __nv_bfloat16 pv = __float2bfloat16(p);
        pb[c * DEMB + j] = pv;
        float pf = __bfloat162float(pv);
        s += pf * pf;
    }
    if (threadIdx.x == 0) qcount[c] = 0.f;
    __shared__ float red[8];
#pragma unroll
    for (int o2 = 16; o2; o2 >>= 1) s += __shfl_xor_sync(~0u, s, o2);
    if ((threadIdx.x & 31) == 0) red[threadIdx.x >> 5] = s;
    __syncthreads();
    if (threadIdx.x < 8) {
        s = red[threadIdx.x];
#pragma unroll
        for (int o2 = 4; o2; o2 >>= 1) s += __shfl_xor_sync(0xff, s, o2);
        if (threadIdx.x == 0) pnorm[c] = s;
    }
}

// segment-sum of query embeddings by label.
__global__ void __launch_bounds__(128) k_segsum2(const __nv_bfloat16* __restrict__ qemb,
                                                 const int* __restrict__ lab,
                                                 float* __restrict__ qsum) {
    extern __shared__ float sacc[];  // 2 banks * NCLS * 256 floats = 128KB
    const int tid = threadIdx.x;
    for (int i = tid; i < 2 * NCLS * 256; i += 128) sacc[i] = 0.f;
    __syncthreads();
    float* a0 = sacc;
    float* a1 = sacc + NCLS * 256;
    const int colpair = blockIdx.x * 128 + tid;
    const __nv_bfloat162* q2 = (const __nv_bfloat162*)qemb;
    const int rpb = NQRY / gridDim.y;
    const int r0 = blockIdx.y * rpb;
    for (int r = r0; r < r0 + rpb; r += 2) {
        int L0 = __ldg(&lab[r]), L1 = __ldg(&lab[r + 1]);
        float2 v0 = __bfloat1622float2(q2[(size_t)r * 512 + colpair]);
        float2 v1 = __bfloat1622float2(q2[(size_t)(r + 1) * 512 + colpair]);
        float* p0 = &a0[L0 * 256 + tid * 2];
        p0[0] += v0.x; p0[1] += v0.y;
        float* p1 = &a1[L1 * 256 + tid * 2];
        p1[0] += v1.x; p1[1] += v1.y;
    }
    __syncthreads();
    for (int i = tid; i < NCLS * 256; i += 128) {
        int cls = i >> 8, cidx = i & 255;
        atomicAdd(&qsum[cls * DEMB + blockIdx.x * 256 + cidx], a0[i] + a1[i]);
    }
}

// ---------------- bf16 HMMA GEMM (mma.sync m16n8k16), swizzled smem ----------------
// MODE 0: merged embedding GEMM. blockIdx.y < nqy -> query rows (writes qemb + qnorm);
//         else -> support rows (writes semb). bias fused.
// MODE 1: labels[m] = argmin_n (pnorm[n] - 2*C), qcount histogram
// MODE 2: outf[m*NCLS+n] = -sqrt(max(qnorm[m]+pnorm[n]-2*C, 1e-12))
#define CP_ASYNC(dst, src) asm volatile("cp.async.cg.shared.global [%0], [%1], 16;\n" ::"r"(dst), "l"(src))

template <int BM, int BN, int WMT, int WNT, int MODE>
__global__ void __launch_bounds__(WMT* WNT * 32, 1) k_gemm(
    const __nv_bfloat16* __restrict__ A, const __nv_bfloat16* __restrict__ B, int K,
    const float* __restrict__ bias, __nv_bfloat16* __restrict__ outb, int ldo,
    const float* __restrict__ pnorm, int* __restrict__ labels, float* __restrict__ qcount,
    float* __restrict__ qnorm, float* __restrict__ outf,
    const __nv_bfloat16* __restrict__ A2, __nv_bfloat16* __restrict__ outb2, int nqy) {
    constexpr int NT = WMT * WNT * 32;
    constexpr int WM = BM / WMT, WN = BN / WNT;
    constexpr int MF = WM / 16, NF = WN / 8;
    constexpr int AIT = BM * 8 / NT;
    constexpr int BIT = BN * 8 / NT;
    constexpr uint32_t STAGE = (BM + BN) * 128;

    extern __shared__ char smem_raw[];
    uint32_t sbase = (uint32_t)__cvta_generic_to_shared(smem_raw);

    const int tid = threadIdx.x;
    const int warp = tid >> 5, lane = tid & 31;
    const int wm = (warp / WNT) * WM, wn = (warp % WNT) * WN;
    const int bn0 = blockIdx.x * BN;

    bool isq = true;
    int ybase = blockIdx.y;
    const __nv_bfloat16* Asel = A;
    __nv_bfloat16* osel = outb;
    if (MODE == 0 && (int)blockIdx.y >= nqy) {
        isq = false;
        ybase = blockIdx.y - nqy;
        Asel = A2;
        osel = outb2;
    }
    const int bm0 = ybase * BM;

    const __nv_bfloat16* Ab = Asel + (size_t)bm0 * K;
    const __nv_bfloat16* Bb = B + (size_t)bn0 * K;

    float acc[MF][NF][4];
#pragma unroll
    for (int i = 0; i < MF; i++)
#pragma unroll
        for (int j = 0; j < NF; j++)
#pragma unroll
            for (int q = 0; q < 4; q++) acc[i][j][q] = 0.f;

    const int KT = K >> 6;  // BK=64

    auto load = [&](int kt) {
        uint32_t sA = sbase + (kt % 3) * STAGE;
        uint32_t sB = sA + (uint32_t)BM * 128u;
        const __nv_bfloat16* Ap = Ab + (size_t)kt * 64;
        const __nv_bfloat16* Bp = Bb + (size_t)kt * 64;
#pragma unroll
        for (int i = 0; i < AIT; i++) {
            int idx = tid + i * NT;
            int r = idx >> 3, c = idx & 7;
            CP_ASYNC(sA + (uint32_t)(r * 128 + ((c ^ (r & 7)) * 16)), Ap + (size_t)r * K + c * 8);
        }
#pragma unroll
        for (int i = 0; i < BIT; i++) {
            int idx = tid + i * NT;
            int r = idx >> 3, c = idx & 7;
            CP_ASYNC(sB + (uint32_t)(r * 128 + ((c ^ (r & 7)) * 16)), Bp + (size_t)r * K + c * 8);
        }
        asm volatile("cp.async.commit_group;\n");
    };

    load(0);
    load(1);
    for (int kt = 0; kt < KT; kt++) {
        if (kt < KT - 1)
            asm volatile("cp.async.wait_group 1;\n" ::: "memory");
        else
            asm volatile("cp.async.wait_group 0;\n" ::: "memory");
        __syncthreads();
        if (kt + 2 < KT) load(kt + 2);  // writes stage (kt-1)%3: already drained
        uint32_t aBase = sbase + (kt % 3) * STAGE;
        uint32_t bBase = aBase + (uint32_t)BM * 128u;
#pragma unroll
        for (int ks = 0; ks < 4; ks++) {
            uint32_t af[MF][4];
#pragma unroll
            for (int mi = 0; mi < MF; mi++) {
                int row = wm + mi * 16 + (lane & 15);
                int ch = (ks * 2 + (lane >> 4)) ^ (row & 7);
                uint32_t adr = aBase + (uint32_t)(row * 128 + ch * 16);
                asm volatile("ldmatrix.sync.aligned.m8n8.x4.shared.b16 {%0,%1,%2,%3},[%4];"
                             : "=r"(af[mi][0]), "=r"(af[mi][1]), "=r"(af[mi][2]), "=r"(af[mi][3])
                             : "r"(adr));
            }
            uint32_t bfr[NF][2];
#pragma unroll
            for (int ni2 = 0; ni2 < NF / 2; ni2++) {
                int nrow = wn + ni2 * 16 + (lane & 7) + ((lane >> 4) << 3);
                int ch = (ks * 2 + ((lane >> 3) & 1)) ^ (nrow & 7);
                uint32_t bd = bBase + (uint32_t)(nrow * 128 + ch * 16);
                uint32_t r0, r1, r2, r3;
                asm volatile("ldmatrix.sync.aligned.m8n8.x4.shared.b16 {%0,%1,%2,%3},[%4];"
                             : "=r"(r0), "=r"(r1), "=r"(r2), "=r"(r3)
                             : "r"(bd));
                bfr[2 * ni2][0] = r0; bfr[2 * ni2][1] = r1;
                bfr[2 * ni2 + 1][0] = r2; bfr[2 * ni2 + 1][1] = r3;
            }
#pragma unroll
            for (int mi = 0; mi < MF; mi++)
#pragma unroll
                for (int ni = 0; ni < NF; ni++)
                    asm volatile(
                        "mma.sync.aligned.m16n8k16.row.col.f32.bf16.bf16.f32 "
                        "{%0,%1,%2,%3},{%4,%5,%6,%7},{%8,%9},{%0,%1,%2,%3};"
                        : "+f"(acc[mi][ni][0]), "+f"(acc[mi][ni][1]),
                          "+f"(acc[mi][ni][2]), "+f"(acc[mi][ni][3])
                        : "r"(af[mi][0]), "r"(af[mi][1]), "r"(af[mi][2]), "r"(af[mi][3]),
                          "r"(bfr[ni][0]), "r"(bfr[ni][1]));
        }
    }

    if (MODE == 0) {
#pragma unroll
        for (int mi = 0; mi < MF; mi++) {
            int row = bm0 + wm + mi * 16 + (lane >> 2);
#pragma unroll
            for (int h = 0; h < 2; h++) {
                int rr = row + h * 8;
                float rs = 0.f;
#pragma unroll
                for (int ni = 0; ni < NF; ni++) {
                    int col = bn0 + wn + ni * 8 + (lane & 3) * 2;
                    float b0v = __ldg(&bias[col]), b1v = __ldg(&bias[col + 1]);
                    __nv_bfloat162 p = __floats2bfloat162_rn(acc[mi][ni][2 * h] + b0v,
                                                             acc[mi][ni][2 * h + 1] + b1v);
                    *(__nv_bfloat162*)(osel + (size_t)rr * ldo + col) = p;
                    float x = __bfloat162float(p.x), y = __bfloat162float(p.y);
                    rs += x * x + y * y;
                }
                if (isq) {
                    rs += __shfl_xor_sync(~0u, rs, 1);
                    rs += __shfl_xor_sync(~0u, rs, 2);
                    if ((lane & 3) == 0) atomicAdd(&qnorm[rr], rs);
                }
            }
        }
    } else if (MODE == 1) {
        float bv[MF][2];
        int bc[MF][2];
#pragma unroll
        for (int mi = 0; mi < MF; mi++)
#pragma unroll
            for (int h = 0; h < 2; h++) { bv[mi][h] = 1e30f; bc[mi][h] = 0; }
#pragma unroll
        for (int mi = 0; mi < MF; mi++)
#pragma unroll
            for (int ni = 0; ni < NF; ni++)
#pragma unroll
                for (int h = 0; h < 2; h++)
#pragma unroll
                    for (int j = 0; j < 2; j++) {
                        int c = wn + ni * 8 + (lane & 3) * 2 + j;
                        float m = pnorm[c] - 2.f * acc[mi][ni][2 * h + j];
                        if (m < bv[mi][h]) { bv[mi][h] = m; bc[mi][h] = c; }
                    }
#pragma unroll
        for (int off = 1; off <= 2; off <<= 1)
#pragma unroll
            for (int mi = 0; mi < MF; mi++)
#pragma unroll
                for (int h = 0; h < 2; h++) {
                    float ov = __shfl_xor_sync(~0u, bv[mi][h], off);
                    int oc = __shfl_xor_sync(~0u, bc[mi][h], off);
                    if (ov < bv[mi][h] || (ov == bv[mi][h] && oc < bc[mi][h])) {
                        bv[mi][h] = ov; bc[mi][h] = oc;
                    }
                }
        __syncthreads();
        float* redv = (float*)smem_raw;
        int* redi = (int*)smem_raw + BM * WNT;
        __shared__ int hist[NCLS];
        if (tid < NCLS) hist[tid] = 0;
        if ((lane & 3) == 0) {
#pragma unroll
            for (int mi = 0; mi < MF; mi++)
#pragma unroll
                for (int h = 0; h < 2; h++) {
                    int r = wm + mi * 16 + (lane >> 2) + 8 * h;
                    redv[r * WNT + (warp % WNT)] = bv[mi][h];
                    redi[r * WNT + (warp % WNT)] = bc[mi][h];
                }
        }
        __syncthreads();
        if (tid < BM) {
            float v = redv[tid * WNT];
            int cbest = redi[tid * WNT];
#pragma unroll
            for (int w2 = 1; w2 < WNT; w2++) {
                float ov = redv[tid * WNT + w2];
                int oc = redi[tid * WNT + w2];
                if (ov < v || (ov == v && oc < cbest)) { v = ov; cbest = oc; }
            }
            labels[bm0 + tid] = cbest;
            atomicAdd(&hist[cbest], 1);
        }
        __syncthreads();
        if (tid < NCLS) atomicAdd(&qcount[tid], (float)hist[tid]);
    } else {  // MODE 2
#pragma unroll
        for (int mi = 0; mi < MF; mi++) {
            int row = bm0 + wm + mi * 16 + (lane >> 2);
#pragma unroll
            for (int h = 0; h < 2; h++) {
                int rr = row + 8 * h;
                float qn = __ldg(&qnorm[rr]);
#pragma unroll
                for (int ni = 0; ni < NF; ni++)
#pragma unroll
                    for (int j = 0; j < 2; j++) {
                        int c = wn + ni * 8 + (lane & 3) * 2 + j;
                        float d2 = qn + pnorm[c] - 2.f * acc[mi][ni][2 * h + j];
                        outf[(size_t)rr * NCLS + c] = -sqrtf(fmaxf(d2, 1e-12f));
                    }
            }
        }
    }
}

// ---------------- host orchestration ----------------
extern "C" void kernel_launch(void* const* d_in, const int* in_sizes, int n_in,
                              void* d_out, int out_size) {
    (void)in_sizes; (void)n_in; (void)out_size;
    const float* support = (const float*)d_in[0];
    const float* query = (const float*)d_in[1];
    const int* slab = (const int*)d_in[2];
    const float* W = (const float*)d_in[3];
    const float* bias = (const float*)d_in[4];
    float* out = (float*)d_out;

    __nv_bfloat16 *Wt, *qx, *sx, *qemb, *semb, *pb;
    float *qnorm, *ssum, *scount, *qsum, *qcount, *pnorm;
    int* labels;
    cudaGetSymbolAddress((void**)&Wt, g_Wt);
    cudaGetSymbolAddress((void**)&qx, g_qx);
    cudaGetSymbolAddress((void**)&sx, g_sx);
    cudaGetSymbolAddress((void**)&qemb, g_qemb);
    cudaGetSymbolAddress((void**)&semb, g_semb);
    cudaGetSymbolAddress((void**)&qnorm, g_qnorm);
    cudaGetSymbolAddress((void**)&ssum, g_ssum);
    cudaGetSymbolAddress((void**)&scount, g_scount);
    cudaGetSymbolAddress((void**)&qsum, g_qsum);
    cudaGetSymbolAddress((void**)&qcount, g_qcount);
    cudaGetSymbolAddress((void**)&pb, g_pb);
    cudaGetSymbolAddress((void**)&pnorm, g_pnorm);
    cudaGetSymbolAddress((void**)&labels, g_labels);

    const int SMEM_BIG = 3 * (128 + 256) * 128;   // 147456
    const int SMEM_SML = 3 * (128 + 64) * 128;    // 73728
    const int SMEM_SEG = 2 * NCLS * 256 * 4;      // 131072
    cudaFuncSetAttribute(k_gemm<128, 256, 2, 4, 0>, cudaFuncAttributeMaxDynamicSharedMemorySize, SMEM_BIG);
    cudaFuncSetAttribute(k_gemm<128, 64, 4, 2, 1>, cudaFuncAttributeMaxDynamicSharedMemorySize, SMEM_SML);
    cudaFuncSetAttribute(k_gemm<128, 64, 4, 2, 2>, cudaFuncAttributeMaxDynamicSharedMemorySize, SMEM_SML);
    cudaFuncSetAttribute(k_segsum2, cudaFuncAttributeMaxDynamicSharedMemorySize, SMEM_SEG);

    // (launch order matters only for the profiler: index 3 = merged GEMM)
    k_convert<<<(NQRY * DIN / 4 + 255) / 256, 256>>>(query, qx, NQRY * DIN / 4);
    k_convert<<<(NSUP * DIN / 4 + 255) / 256, 256>>>(support, sx, NSUP * DIN / 4);
    k_transpose_w<<<dim3(DEMB / 32, DIN / 32), dim3(32, 8)>>>(W, Wt, qnorm);

    // merged embedding GEMM (query y-blocks [0,512), support [512,522))
    k_gemm<128, 256, 2, 4, 0><<<dim3(DEMB / 256, QYB + NSUP / 128), 256, SMEM_BIG>>>(
        qx, Wt, DIN, bias, qemb, DEMB, nullptr, nullptr, nullptr, qnorm, nullptr,
        sx, semb, QYB);

    // support class sums + counts -> initial prototypes (also zeroes qsum/qcount)
    k_zero<<<(NCLS * DEMB + 255) / 256, 256>>>(ssum, NCLS * DEMB);
    k_zero<<<1, 64>>>(scount, NCLS);
    k_supp_stats<<<NSUP, 256>>>(semb, slab, ssum, scount);
    k_proto<<<NCLS, 256>>>(ssum, scount, qsum, qcount, 0, pb, pnorm);

    for (int s = 0; s < NSTEPS; s++) {
        k_gemm<128, 64, 4, 2, 1><<<dim3(1, NQRY / 128), 256, SMEM_SML>>>(
            qemb, pb, DEMB, nullptr, nullptr, 0, pnorm, labels, qcount, nullptr, nullptr,
            nullptr, nullptr, 1 << 20);
        k_segsum2<<<dim3(DEMB / 256, 32), 128, SMEM_SEG>>>(qemb, labels, qsum);
        k_proto<<<NCLS, 256>>>(ssum, scount, qsum, qcount, 1, pb, pnorm);
    }

    // final logits
    k_gemm<128, 64, 4, 2, 2><<<dim3(1, NQRY / 128), 256, SMEM_SML>>>(
        qemb, pb, DEMB, nullptr, nullptr, 0, pnorm, nullptr, nullptr, qnorm, out,
        nullptr, nullptr, 1 << 20);
}

// round 7
// speedup vs baseline: 1.5271x; 1.4814x over previous
#include <cuda_runtime.h>
#include <cuda_bf16.h>
#include <stdint.h>

#define NSUP   1280
#define NQRY   65536
#define DIN    2048
#define DEMB   1024
#define NCLS   64
#define NSTEPS 5
#define QYB    (NQRY / 128)   // 512 query y-blocks

// ---------------- scratch (device globals; no allocation) ----------------
__device__ __align__(256) __nv_bfloat16 g_Wt[(size_t)DEMB * DIN];      // [DEMB][DIN]
__device__ __align__(256) __nv_bfloat16 g_qx[(size_t)NQRY * DIN];
__device__ __align__(256) __nv_bfloat16 g_sx[(size_t)NSUP * DIN];
__device__ __align__(256) __nv_bfloat16 g_qemb[(size_t)NQRY * DEMB];
__device__ __align__(256) __nv_bfloat16 g_semb[(size_t)NSUP * DEMB];
__device__ float g_qnorm[NQRY];
__device__ float g_ssum[NCLS * DEMB];
__device__ float g_scount[NCLS];
__device__ float g_qsum[NCLS * DEMB];
__device__ float g_qcount[NCLS];
__device__ __align__(256) __nv_bfloat16 g_pb[NCLS * DEMB];             // prototypes bf16
__device__ float g_pnorm[NCLS];

#define CP_ASYNC(dst, src) asm volatile("cp.async.cg.shared.global [%0], [%1], 16;\n" ::"r"(dst), "l"(src))

// ---------------- small utility kernels ----------------
__global__ void k_convert(const float* __restrict__ x, __nv_bfloat16* __restrict__ y, int n4) {
    int i = blockIdx.x * blockDim.x + threadIdx.x;
    if (i < n4) {
        float4 v = ((const float4*)x)[i];
        ((__nv_bfloat162*)y)[2 * i + 0] = __floats2bfloat162_rn(v.x, v.y);
        ((__nv_bfloat162*)y)[2 * i + 1] = __floats2bfloat162_rn(v.z, v.w);
    }
}

// tiled transpose: W [DIN][DEMB] f32 -> Wt [DEMB][DIN] bf16.
// Side task: zeroes qnorm (65536), ssum (65536), scount (64).
__global__ void k_transpose_w(const float* __restrict__ W, __nv_bfloat16* __restrict__ Wt,
                              float* __restrict__ qnorm, float* __restrict__ ssum,
                              float* __restrict__ scount) {
    __shared__ float tile[32][33];
    int n0 = blockIdx.x * 32, k0 = blockIdx.y * 32;
#pragma unroll
    for (int i = 0; i < 4; i++) {
        int k = k0 + threadIdx.y + i * 8;
        tile[threadIdx.y + i * 8][threadIdx.x] = W[(size_t)k * DEMB + n0 + threadIdx.x];
    }
    // zero side-work: 2048 blocks, 64 floats each = 131072, plus block 0 does scount
    {
        int bid = blockIdx.y * gridDim.x + blockIdx.x;
        int t = threadIdx.y * 32 + threadIdx.x;  // 0..255
        if (t < 64) {
            int gi = bid * 64 + t;
            if (gi < NQRY) qnorm[gi] = 0.f;
            else if (gi < 2 * NQRY) { /* unreachable for 2048*64=131072; split below */ }
            if (gi < NCLS * DEMB) ssum[gi] = 0.f;
            if (bid == 0 && t < NCLS) scount[t] = 0.f;
        }
    }
    __syncthreads();
#pragma unroll
    for (int i = 0; i < 4; i++) {
        int n = n0 + threadIdx.y + i * 8;
        Wt[(size_t)n * DIN + k0 + threadIdx.x] =
            __float2bfloat16(tile[threadIdx.x][threadIdx.y + i * 8]);
    }
}

__global__ void k_supp_stats(const __nv_bfloat16* __restrict__ semb, const int* __restrict__ lab,
                             float* __restrict__ ssum, float* __restrict__ scount) {
    int r = blockIdx.x;
    int L = lab[r];
    if (threadIdx.x == 0) atomicAdd(&scount[L], 1.0f);
    for (int c = threadIdx.x; c < DEMB; c += blockDim.x)
        atomicAdd(&ssum[L * DEMB + c], __bfloat162float(semb[(size_t)r * DEMB + c]));
}

// prototypes from (ssum [+ qsum]) / counts; ALSO zeroes qsum/qcount for the next pass.
__global__ void k_proto(const float* __restrict__ ssum, const float* __restrict__ scount,
                        float* __restrict__ qsum, float* __restrict__ qcount,
                        int useq, __nv_bfloat16* __restrict__ pb, float* __restrict__ pnorm) {
    int c = blockIdx.x;
    float cnt = scount[c] + (useq ? qcount[c] : 0.f);
    float inv = 1.f / fmaxf(cnt, 1.f);
    float s = 0.f;
    for (int j = threadIdx.x; j < DEMB; j += blockDim.x) {
        float p = (ssum[c * DEMB + j] + (useq ? qsum[c * DEMB + j] : 0.f)) * inv;
        qsum[c * DEMB + j] = 0.f;
        __nv_bfloat16 pv = __float2bfloat16(p);
        pb[c * DEMB + j] = pv;
        float pf = __bfloat162float(pv);
        s += pf * pf;
    }
    if (threadIdx.x == 0) qcount[c] = 0.f;
    __shared__ float red[8];
#pragma unroll
    for (int o2 = 16; o2; o2 >>= 1) s += __shfl_xor_sync(~0u, s, o2);
    if ((threadIdx.x & 31) == 0) red[threadIdx.x >> 5] = s;
    __syncthreads();
    if (threadIdx.x < 8) {
        s = red[threadIdx.x];
#pragma unroll
        for (int o2 = 4; o2; o2 >>= 1) s += __shfl_xor_sync(0xff, s, o2);
        if (threadIdx.x == 0) pnorm[c] = s;
    }
}

// ================= fused transductive step =================
// One CTA owns 256 query rows. Phase A: HMMA GEMM q@p^T (K=1024), argmin margin
// -> labels in smem + qcount. Phase B: re-read own rows (L2-hot), accumulate
// per-class sums in smem float2 bins, flush to qsum via atomics.
// grid (1, 256), 256 threads, dynamic smem 131072 B.
#define STP_STAGE ((256 + 64) * 128)   // 40960 B per stage (A 32KB + B 8KB)
#define STP_SMEM  131072

__global__ void __launch_bounds__(256, 1) k_step(
    const __nv_bfloat16* __restrict__ qemb, const __nv_bfloat16* __restrict__ pb,
    const float* __restrict__ pnorm, float* __restrict__ qsum, float* __restrict__ qcount) {
    extern __shared__ char smem_raw[];
    uint32_t sbase = (uint32_t)__cvta_generic_to_shared(smem_raw);
    __shared__ short labels_s[256];
    __shared__ int hist[NCLS];

    const int tid = threadIdx.x;
    const int warp = tid >> 5, lane = tid & 31;
    const int wm = warp * 32;                 // WM=32, WN=64 (all classes)
    const int bm0 = blockIdx.y * 256;
    const __nv_bfloat16* Ab = qemb + (size_t)bm0 * DIN / 2;  // careful: K=DEMB here
    // (rewritten below with correct K)
    const __nv_bfloat16* A = qemb + (size_t)bm0 * DEMB;

    if (tid < NCLS) hist[tid] = 0;

    float acc[2][8][4];
#pragma unroll
    for (int i = 0; i < 2; i++)
#pragma unroll
        for (int j = 0; j < 8; j++)
#pragma unroll
            for (int q = 0; q < 4; q++) acc[i][j][q] = 0.f;

    const int KT = DEMB >> 6;  // 16

    auto load = [&](int kt) {
        uint32_t sA = sbase + (kt % 3) * STP_STAGE;
        uint32_t sB = sA + 256u * 128u;
        const __nv_bfloat16* Ap = A + (size_t)kt * 64;
        const __nv_bfloat16* Bp = pb + (size_t)kt * 64;
#pragma unroll
        for (int i = 0; i < 8; i++) {  // A: 256 rows * 8 chunks / 256 thr
            int idx = tid + i * 256;
            int r = idx >> 3, c = idx & 7;
            CP_ASYNC(sA + (uint32_t)(r * 128 + ((c ^ (r & 7)) * 16)), Ap + (size_t)r * DEMB + c * 8);
        }
#pragma unroll
        for (int i = 0; i < 2; i++) {  // B: 64 rows * 8 chunks / 256 thr
            int idx = tid + i * 256;
            int r = idx >> 3, c = idx & 7;
            CP_ASYNC(sB + (uint32_t)(r * 128 + ((c ^ (r & 7)) * 16)), Bp + (size_t)r * DEMB + c * 8);
        }
        asm volatile("cp.async.commit_group;\n");
    };

    load(0);
    load(1);
    for (int kt = 0; kt < KT; kt++) {
        if (kt < KT - 1)
            asm volatile("cp.async.wait_group 1;\n" ::: "memory");
        else
            asm volatile("cp.async.wait_group 0;\n" ::: "memory");
        __syncthreads();
        if (kt + 2 < KT) load(kt + 2);
        uint32_t aBase = sbase + (kt % 3) * STP_STAGE;
        uint32_t bBase = aBase + 256u * 128u;
#pragma unroll
        for (int ks = 0; ks < 4; ks++) {
            uint32_t af[2][4];
#pragma unroll
            for (int mi = 0; mi < 2; mi++) {
                int row = wm + mi * 16 + (lane & 15);
                int ch = (ks * 2 + (lane >> 4)) ^ (row & 7);
                uint32_t adr = aBase + (uint32_t)(row * 128 + ch * 16);
                asm volatile("ldmatrix.sync.aligned.m8n8.x4.shared.b16 {%0,%1,%2,%3},[%4];"
                             : "=r"(af[mi][0]), "=r"(af[mi][1]), "=r"(af[mi][2]), "=r"(af[mi][3])
                             : "r"(adr));
            }
            uint32_t bfr[8][2];
#pragma unroll
            for (int ni2 = 0; ni2 < 4; ni2++) {
                int nrow = ni2 * 16 + (lane & 7) + ((lane >> 4) << 3);
                int ch = (ks * 2 + ((lane >> 3) & 1)) ^ (nrow & 7);
                uint32_t bd = bBase + (uint32_t)(nrow * 128 + ch * 16);
                uint32_t r0, r1, r2, r3;
                asm volatile("ldmatrix.sync.aligned.m8n8.x4.shared.b16 {%0,%1,%2,%3},[%4];"
                             : "=r"(r0), "=r"(r1), "=r"(r2), "=r"(r3)
                             : "r"(bd));
                bfr[2 * ni2][0] = r0; bfr[2 * ni2][1] = r1;
                bfr[2 * ni2 + 1][0] = r2; bfr[2 * ni2 + 1][1] = r3;
            }
#pragma unroll
            for (int mi = 0; mi < 2; mi++)
#pragma unroll
                for (int ni = 0; ni < 8; ni++)
                    asm volatile(
                        "mma.sync.aligned.m16n8k16.row.col.f32.bf16.bf16.f32 "
                        "{%0,%1,%2,%3},{%4,%5,%6,%7},{%8,%9},{%0,%1,%2,%3};"
                        : "+f"(acc[mi][ni][0]), "+f"(acc[mi][ni][1]),
                          "+f"(acc[mi][ni][2]), "+f"(acc[mi][ni][3])
                        : "r"(af[mi][0]), "r"(af[mi][1]), "r"(af[mi][2]), "r"(af[mi][3]),
                          "r"(bfr[ni][0]), "r"(bfr[ni][1]));
        }
    }

    // argmin over 64 classes (margin = pnorm - 2*dot), tie -> lowest index
    {
        float bv[2][2];
        int bc[2][2];
#pragma unroll
        for (int mi = 0; mi < 2; mi++)
#pragma unroll
            for (int h = 0; h < 2; h++) { bv[mi][h] = 1e30f; bc[mi][h] = 0; }
#pragma unroll
        for (int ni = 0; ni < 8; ni++)
#pragma unroll
            for (int j = 0; j < 2; j++) {
                int c = ni * 8 + (lane & 3) * 2 + j;
                float pn = __ldg(&pnorm[c]);
#pragma unroll
                for (int mi = 0; mi < 2; mi++)
#pragma unroll
                    for (int h = 0; h < 2; h++) {
                        float m = pn - 2.f * acc[mi][ni][2 * h + j];
                        if (m < bv[mi][h]) { bv[mi][h] = m; bc[mi][h] = c; }
                    }
            }
#pragma unroll
        for (int off = 1; off <= 2; off <<= 1)
#pragma unroll
            for (int mi = 0; mi < 2; mi++)
#pragma unroll
                for (int h = 0; h < 2; h++) {
                    float ov = __shfl_xor_sync(~0u, bv[mi][h], off);
                    int oc = __shfl_xor_sync(~0u, bc[mi][h], off);
                    if (ov < bv[mi][h] || (ov == bv[mi][h] && oc < bc[mi][h])) {
                        bv[mi][h] = ov; bc[mi][h] = oc;
                    }
                }
        if ((lane & 3) == 0) {
#pragma unroll
            for (int mi = 0; mi < 2; mi++)
#pragma unroll
                for (int h = 0; h < 2; h++) {
                    int row = wm + mi * 16 + (lane >> 2) + 8 * h;
                    labels_s[row] = (short)bc[mi][h];
                    atomicAdd(&hist[bc[mi][h]], 1);
                }
        }
    }
    __syncthreads();
    if (tid < NCLS) atomicAdd(&qcount[tid], (float)hist[tid]);

    // ---- Phase B: per-class accumulate of own 256 rows ----
    // bins[rg][cls][cp]: 4 row-groups x 64 classes x 64 float2 = 128KB (reuses stages)
    float2* bins = (float2*)smem_raw;
    const int rg = tid >> 6;        // 0..3 (rows rg*64 .. rg*64+63)
    const int cp = tid & 63;        // bf162 column within 64-pair chunk
    const __nv_bfloat162* q2 = (const __nv_bfloat162*)(qemb) + (size_t)bm0 * 512;
#pragma unroll 1
    for (int chunk = 0; chunk < 8; chunk++) {
        for (int i = tid; i < 4 * NCLS * 64; i += 256) {
            bins[i].x = 0.f; bins[i].y = 0.f;
        }
        __syncthreads();
        float2* mybins = bins + rg * NCLS * 64 + cp;
#pragma unroll 4
        for (int r = 0; r < 64; r++) {
            int row = rg * 64 + r;
            int L = labels_s[row];
            float2 v = __bfloat1622float2(q2[(size_t)row * 512 + chunk * 64 + cp]);
            float2* b = mybins + L * 64;
            b->x += v.x; b->y += v.y;
        }
        __syncthreads();
        // flush: sum 4 row-groups, atomic to qsum
        for (int i = tid; i < NCLS * 64; i += 256) {
            int cls = i >> 6, cc = i & 63;
            float2 s = bins[cls * 64 + cc];
            float2 s1 = bins[(NCLS + cls) * 64 + cc];
            float2 s2 = bins[(2 * NCLS + cls) * 64 + cc];
            float2 s3 = bins[(3 * NCLS + cls) * 64 + cc];
            float sx = s.x + s1.x + s2.x + s3.x;
            float sy = s.y + s1.y + s2.y + s3.y;
            float* dst = &qsum[cls * DEMB + chunk * 128 + cc * 2];
            atomicAdd(dst, sx);
            atomicAdd(dst + 1, sy);
        }
        __syncthreads();
    }
    (void)Ab;
}

// ---------------- bf16 HMMA GEMM (embedding + logits) ----------------
// MODE 0: merged embedding GEMM (query + support), bias fused, qnorm accumulated
// MODE 2: outf[m*NCLS+n] = -sqrt(max(qnorm[m]+pnorm[n]-2*C, 1e-12))
template <int BM, int BN, int WMT, int WNT, int MODE>
__global__ void __launch_bounds__(WMT* WNT * 32, 1) k_gemm(
    const __nv_bfloat16* __restrict__ A, const __nv_bfloat16* __restrict__ B, int K,
    const float* __restrict__ bias, __nv_bfloat16* __restrict__ outb, int ldo,
    const float* __restrict__ pnorm, float* __restrict__ qnorm, float* __restrict__ outf,
    const __nv_bfloat16* __restrict__ A2, __nv_bfloat16* __restrict__ outb2, int nqy) {
    constexpr int NT = WMT * WNT * 32;
    constexpr int WM = BM / WMT, WN = BN / WNT;
    constexpr int MF = WM / 16, NF = WN / 8;
    constexpr int AIT = BM * 8 / NT;
    constexpr int BIT = BN * 8 / NT;
    constexpr uint32_t STAGE = (BM + BN) * 128;

    extern __shared__ char smem_raw[];
    uint32_t sbase = (uint32_t)__cvta_generic_to_shared(smem_raw);

    const int tid = threadIdx.x;
    const int warp = tid >> 5, lane = tid & 31;
    const int wm = (warp / WNT) * WM, wn = (warp % WNT) * WN;
    const int bn0 = blockIdx.x * BN;

    bool isq = true;
    int ybase = blockIdx.y;
    const __nv_bfloat16* Asel = A;
    __nv_bfloat16* osel = outb;
    if (MODE == 0 && (int)blockIdx.y >= nqy) {
        isq = false;
        ybase = blockIdx.y - nqy;
        Asel = A2;
        osel = outb2;
    }
    const int bm0 = ybase * BM;

    const __nv_bfloat16* Ab = Asel + (size_t)bm0 * K;
    const __nv_bfloat16* Bb = B + (size_t)bn0 * K;

    float acc[MF][NF][4];
#pragma unroll
    for (int i = 0; i < MF; i++)
#pragma unroll
        for (int j = 0; j < NF; j++)
#pragma unroll
            for (int q = 0; q < 4; q++) acc[i][j][q] = 0.f;

    const int KT = K >> 6;

    auto load = [&](int kt) {
        uint32_t sA = sbase + (kt % 3) * STAGE;
        uint32_t sB = sA + (uint32_t)BM * 128u;
        const __nv_bfloat16* Ap = Ab + (size_t)kt * 64;
        const __nv_bfloat16* Bp = Bb + (size_t)kt * 64;
#pragma unroll
        for (int i = 0; i < AIT; i++) {
            int idx = tid + i * NT;
            int r = idx >> 3, c = idx & 7;
            CP_ASYNC(sA + (uint32_t)(r * 128 + ((c ^ (r & 7)) * 16)), Ap + (size_t)r * K + c * 8);
        }
#pragma unroll
        for (int i = 0; i < BIT; i++) {
            int idx = tid + i * NT;
            int r = idx >> 3, c = idx & 7;
            CP_ASYNC(sB + (uint32_t)(r * 128 + ((c ^ (r & 7)) * 16)), Bp + (size_t)r * K + c * 8);
        }
        asm volatile("cp.async.commit_group;\n");
    };

    load(0);
    load(1);
    for (int kt = 0; kt < KT; kt++) {
        if (kt < KT - 1)
            asm volatile("cp.async.wait_group 1;\n" ::: "memory");
        else
            asm volatile("cp.async.wait_group 0;\n" ::: "memory");
        __syncthreads();
        if (kt + 2 < KT) load(kt + 2);
        uint32_t aBase = sbase + (kt % 3) * STAGE;
        uint32_t bBase = aBase + (uint32_t)BM * 128u;
#pragma unroll
        for (int ks = 0; ks < 4; ks++) {
            uint32_t af[MF][4];
#pragma unroll
            for (int mi = 0; mi < MF; mi++) {
                int row = wm + mi * 16 + (lane & 15);
                int ch = (ks * 2 + (lane >> 4)) ^ (row & 7);
                uint32_t adr = aBase + (uint32_t)(row * 128 + ch * 16);
                asm volatile("ldmatrix.sync.aligned.m8n8.x4.shared.b16 {%0,%1,%2,%3},[%4];"
                             : "=r"(af[mi][0]), "=r"(af[mi][1]), "=r"(af[mi][2]), "=r"(af[mi][3])
                             : "r"(adr));
            }
            uint32_t bfr[NF][2];
#pragma unroll
            for (int ni2 = 0; ni2 < NF / 2; ni2++) {
                int nrow = wn + ni2 * 16 + (lane & 7) + ((lane >> 4) << 3);
                int ch = (ks * 2 + ((lane >> 3) & 1)) ^ (nrow & 7);
                uint32_t bd = bBase + (uint32_t)(nrow * 128 + ch * 16);
                uint32_t r0, r1, r2, r3;
                asm volatile("ldmatrix.sync.aligned.m8n8.x4.shared.b16 {%0,%1,%2,%3},[%4];"
                             : "=r"(r0), "=r"(r1), "=r"(r2), "=r"(r3)
                             : "r"(bd));
                bfr[2 * ni2][0] = r0; bfr[2 * ni2][1] = r1;
                bfr[2 * ni2 + 1][0] = r2; bfr[2 * ni2 + 1][1] = r3;
            }
#pragma unroll
            for (int mi = 0; mi < MF; mi++)
#pragma unroll
                for (int ni = 0; ni < NF; ni++)
                    asm volatile(
                        "mma.sync.aligned.m16n8k16.row.col.f32.bf16.bf16.f32 "
                        "{%0,%1,%2,%3},{%4,%5,%6,%7},{%8,%9},{%0,%1,%2,%3};"
                        : "+f"(acc[mi][ni][0]), "+f"(acc[mi][ni][1]),
                          "+f"(acc[mi][ni][2]), "+f"(acc[mi][ni][3])
                        : "r"(af[mi][0]), "r"(af[mi][1]), "r"(af[mi][2]), "r"(af[mi][3]),
                          "r"(bfr[ni][0]), "r"(bfr[ni][1]));
        }
    }

    if (MODE == 0) {
#pragma unroll
        for (int mi = 0; mi < MF; mi++) {
            int row = bm0 + wm + mi * 16 + (lane >> 2);
#pragma unroll
            for (int h = 0; h < 2; h++) {
                int rr = row + h * 8;
                float rs = 0.f;
#pragma unroll
                for (int ni = 0; ni < NF; ni++) {
                    int col = bn0 + wn + ni * 8 + (lane & 3) * 2;
                    float b0v = __ldg(&bias[col]), b1v = __ldg(&bias[col + 1]);
                    __nv_bfloat162 p = __floats2bfloat162_rn(acc[mi][ni][2 * h] + b0v,
                                                             acc[mi][ni][2 * h + 1] + b1v);
                    *(__nv_bfloat162*)(osel + (size_t)rr * ldo + col) = p;
                    float x = __bfloat162float(p.x), y = __bfloat162float(p.y);
                    rs += x * x + y * y;
                }
                if (isq) {
                    rs += __shfl_xor_sync(~0u, rs, 1);
                    rs += __shfl_xor_sync(~0u, rs, 2);
                    if ((lane & 3) == 0) atomicAdd(&qnorm[rr], rs);
                }
            }
        }
    } else {  // MODE 2
#pragma unroll
        for (int mi = 0; mi < MF; mi++) {
            int row = bm0 + wm + mi * 16 + (lane >> 2);
#pragma unroll
            for (int h = 0; h < 2; h++) {
                int rr = row + 8 * h;
                float qn = __ldg(&qnorm[rr]);
#pragma unroll
                for (int ni = 0; ni < NF; ni++)
#pragma unroll
                    for (int j = 0; j < 2; j++) {
                        int c = wn + ni * 8 + (lane & 3) * 2 + j;
                        float d2 = qn + __ldg(&pnorm[c]) - 2.f * acc[mi][ni][2 * h + j];
                        outf[(size_t)rr * NCLS + c] = -sqrtf(fmaxf(d2, 1e-12f));
                    }
            }
        }
    }
}

// ---------------- host orchestration ----------------
extern "C" void kernel_launch(void* const* d_in, const int* in_sizes, int n_in,
                              void* d_out, int out_size) {
    (void)in_sizes; (void)n_in; (void)out_size;
    const float* support = (const float*)d_in[0];
    const float* query = (const float*)d_in[1];
    const int* slab = (const int*)d_in[2];
    const float* W = (const float*)d_in[3];
    const float* bias = (const float*)d_in[4];
    float* out = (float*)d_out;

    __nv_bfloat16 *Wt, *qx, *sx, *qemb, *semb, *pb;
    float *qnorm, *ssum, *scount, *qsum, *qcount, *pnorm;
    cudaGetSymbolAddress((void**)&Wt, g_Wt);
    cudaGetSymbolAddress((void**)&qx, g_qx);
    cudaGetSymbolAddress((void**)&sx, g_sx);
    cudaGetSymbolAddress((void**)&qemb, g_qemb);
    cudaGetSymbolAddress((void**)&semb, g_semb);
    cudaGetSymbolAddress((void**)&qnorm, g_qnorm);
    cudaGetSymbolAddress((void**)&ssum, g_ssum);
    cudaGetSymbolAddress((void**)&scount, g_scount);
    cudaGetSymbolAddress((void**)&qsum, g_qsum);
    cudaGetSymbolAddress((void**)&qcount, g_qcount);
    cudaGetSymbolAddress((void**)&pb, g_pb);
    cudaGetSymbolAddress((void**)&pnorm, g_pnorm);

    const int SMEM_BIG = 3 * (128 + 256) * 128;   // 147456
    const int SMEM_SML = 3 * (128 + 64) * 128;    // 73728
    cudaFuncSetAttribute(k_gemm<128, 256, 2, 4, 0>, cudaFuncAttributeMaxDynamicSharedMemorySize, SMEM_BIG);
    cudaFuncSetAttribute(k_gemm<128, 64, 4, 2, 2>, cudaFuncAttributeMaxDynamicSharedMemorySize, SMEM_SML);
    cudaFuncSetAttribute(k_step, cudaFuncAttributeMaxDynamicSharedMemorySize, STP_SMEM);

    // launch order: profiler captures the 4th launch = merged big GEMM
    k_convert<<<(NQRY * DIN / 4 + 255) / 256, 256>>>(query, qx, NQRY * DIN / 4);
    k_convert<<<(NSUP * DIN / 4 + 255) / 256, 256>>>(support, sx, NSUP * DIN / 4);
    k_transpose_w<<<dim3(DEMB / 32, DIN / 32), dim3(32, 8)>>>(W, Wt, qnorm, ssum, scount);

    // merged embedding GEMM (query y-blocks [0,512), support [512,522))
    k_gemm<128, 256, 2, 4, 0><<<dim3(DEMB / 256, QYB + NSUP / 128), 256, SMEM_BIG>>>(
        qx, Wt, DIN, bias, qemb, DEMB, nullptr, qnorm, nullptr, sx, semb, QYB);

    // support class sums + counts -> initial prototypes (also zeroes qsum/qcount)
    k_supp_stats<<<NSUP, 256>>>(semb, slab, ssum, scount);
    k_proto<<<NCLS, 256>>>(ssum, scount, qsum, qcount, 0, pb, pnorm);

    for (int s = 0; s < NSTEPS; s++) {
        k_step<<<dim3(1, NQRY / 256), 256, STP_SMEM>>>(qemb, pb, pnorm, qsum, qcount);
        k_proto<<<NCLS, 256>>>(ssum, scount, qsum, qcount, 1, pb, pnorm);
    }

    // final logits
    k_gemm<128, 64, 4, 2, 2><<<dim3(1, NQRY / 128), 256, SMEM_SML>>>(
        qemb, pb, DEMB, nullptr, nullptr, 0, pnorm, qnorm, out, nullptr, nullptr, 1 << 20);
}

// round 8
// speedup vs baseline: 1.5664x; 1.0258x over previous
#include <cuda_runtime.h>
#include <cuda_bf16.h>
#include <stdint.h>

#define NSUP   1280
#define NQRY   65536
#define DIN    2048
#define DEMB   1024
#define NCLS   64
#define NSTEPS 5
#define QYB    (NQRY / 128)   // 512 query y-blocks

// ---------------- scratch (device globals; no allocation) ----------------
__device__ __align__(256) __nv_bfloat16 g_Wt[(size_t)DEMB * DIN];      // [DEMB][DIN]
__device__ __align__(256) __nv_bfloat16 g_qx[(size_t)NQRY * DIN];
__device__ __align__(256) __nv_bfloat16 g_sx[(size_t)NSUP * DIN];
__device__ __align__(256) __nv_bfloat16 g_qemb[(size_t)NQRY * DEMB];
__device__ __align__(256) __nv_bfloat16 g_semb[(size_t)NSUP * DEMB];
__device__ float g_qnorm[NQRY];
__device__ float g_ssum[NCLS * DEMB];
__device__ float g_scount[NCLS];
__device__ __align__(16) float g_qsum[NCLS * DEMB];
__device__ float g_qcount[NCLS];
__device__ __align__(256) __nv_bfloat16 g_pb[NCLS * DEMB];             // prototypes bf16
__device__ float g_pnorm[NCLS];

#define CP_ASYNC(dst, src) asm volatile("cp.async.cg.shared.global [%0], [%1], 16;\n" ::"r"(dst), "l"(src))
#define RED_V4(ptr, v) \
    asm volatile("red.global.add.v4.f32 [%0], {%1,%2,%3,%4};" \
                 ::"l"(ptr), "f"((v).x), "f"((v).y), "f"((v).z), "f"((v).w) : "memory")

// ---------------- small utility kernels ----------------
__global__ void k_convert(const float* __restrict__ x, __nv_bfloat16* __restrict__ y, int n4) {
    int i = blockIdx.x * blockDim.x + threadIdx.x;
    if (i < n4) {
        float4 v = ((const float4*)x)[i];
        ((__nv_bfloat162*)y)[2 * i + 0] = __floats2bfloat162_rn(v.x, v.y);
        ((__nv_bfloat162*)y)[2 * i + 1] = __floats2bfloat162_rn(v.z, v.w);
    }
}

// tiled transpose: W [DIN][DEMB] f32 -> Wt [DEMB][DIN] bf16.
// Side task: zeroes qnorm (65536), ssum (65536), scount (64).
__global__ void k_transpose_w(const float* __restrict__ W, __nv_bfloat16* __restrict__ Wt,
                              float* __restrict__ qnorm, float* __restrict__ ssum,
                              float* __restrict__ scount) {
    __shared__ float tile[32][33];
    int n0 = blockIdx.x * 32, k0 = blockIdx.y * 32;
#pragma unroll
    for (int i = 0; i < 4; i++) {
        int k = k0 + threadIdx.y + i * 8;
        tile[threadIdx.y + i * 8][threadIdx.x] = W[(size_t)k * DEMB + n0 + threadIdx.x];
    }
    {
        int bid = blockIdx.y * gridDim.x + blockIdx.x;  // 0..2047
        int t = threadIdx.y * 32 + threadIdx.x;         // 0..255
        if (t < 64) {
            int gi = bid * 64 + t;                      // 0..131071
            if (gi < NQRY) qnorm[gi] = 0.f;
            if (gi < NCLS * DEMB) ssum[gi] = 0.f;
            if (bid == 0 && t < NCLS) scount[t] = 0.f;
        }
    }
    __syncthreads();
#pragma unroll
    for (int i = 0; i < 4; i++) {
        int n = n0 + threadIdx.y + i * 8;
        Wt[(size_t)n * DIN + k0 + threadIdx.x] =
            __float2bfloat16(tile[threadIdx.x][threadIdx.y + i * 8]);
    }
}

__global__ void k_supp_stats(const __nv_bfloat16* __restrict__ semb, const int* __restrict__ lab,
                             float* __restrict__ ssum, float* __restrict__ scount) {
    int r = blockIdx.x;
    int L = lab[r];
    if (threadIdx.x == 0) atomicAdd(&scount[L], 1.0f);
    for (int c = threadIdx.x; c < DEMB; c += blockDim.x)
        atomicAdd(&ssum[L * DEMB + c], __bfloat162float(semb[(size_t)r * DEMB + c]));
}

// prototypes from (ssum [+ qsum]) / counts; ALSO zeroes qsum/qcount for the next pass.
__global__ void k_proto(const float* __restrict__ ssum, const float* __restrict__ scount,
                        float* __restrict__ qsum, float* __restrict__ qcount,
                        int useq, __nv_bfloat16* __restrict__ pb, float* __restrict__ pnorm) {
    int c = blockIdx.x;
    float cnt = scount[c] + (useq ? qcount[c] : 0.f);
    float inv = 1.f / fmaxf(cnt, 1.f);
    float s = 0.f;
    for (int j = threadIdx.x; j < DEMB; j += blockDim.x) {
        float p = (ssum[c * DEMB + j] + (useq ? qsum[c * DEMB + j] : 0.f)) * inv;
        qsum[c * DEMB + j] = 0.f;
        __nv_bfloat16 pv = __float2bfloat16(p);
        pb[c * DEMB + j] = pv;
        float pf = __bfloat162float(pv);
        s += pf * pf;
    }
    if (threadIdx.x == 0) qcount[c] = 0.f;
    __shared__ float red[8];
#pragma unroll
    for (int o2 = 16; o2; o2 >>= 1) s += __shfl_xor_sync(~0u, s, o2);
    if ((threadIdx.x & 31) == 0) red[threadIdx.x >> 5] = s;
    __syncthreads();
    if (threadIdx.x < 8) {
        s = red[threadIdx.x];
#pragma unroll
        for (int o2 = 4; o2; o2 >>= 1) s += __shfl_xor_sync(0xff, s, o2);
        if (threadIdx.x == 0) pnorm[c] = s;
    }
}

// ================= fused transductive step =================
// One CTA owns 256 query rows. Phase A: HMMA GEMM q@p^T (K=1024), argmin margin
// -> labels in smem + qcount. Phase B: re-read own rows (L2-hot), accumulate
// per-class sums in smem float2 bins, flush via red.global.add.v4.f32.
#define STP_STAGE ((256 + 64) * 128)   // 40960 B per stage (A 32KB + B 8KB)
#define STP_SMEM  131072

__global__ void __launch_bounds__(256, 1) k_step(
    const __nv_bfloat16* __restrict__ qemb, const __nv_bfloat16* __restrict__ pb,
    const float* __restrict__ pnorm, float* __restrict__ qsum, float* __restrict__ qcount) {
    extern __shared__ char smem_raw[];
    uint32_t sbase = (uint32_t)__cvta_generic_to_shared(smem_raw);
    __shared__ short labels_s[256];
    __shared__ int hist[NCLS];

    const int tid = threadIdx.x;
    const int warp = tid >> 5, lane = tid & 31;
    const int wm = warp * 32;                 // WM=32, WN=64 (all classes)
    const int bm0 = blockIdx.y * 256;
    const __nv_bfloat16* A = qemb + (size_t)bm0 * DEMB;

    if (tid < NCLS) hist[tid] = 0;

    float acc[2][8][4];
#pragma unroll
    for (int i = 0; i < 2; i++)
#pragma unroll
        for (int j = 0; j < 8; j++)
#pragma unroll
            for (int q = 0; q < 4; q++) acc[i][j][q] = 0.f;

    const int KT = DEMB >> 6;  // 16

    auto load = [&](int kt) {
        uint32_t sA = sbase + (kt % 3) * STP_STAGE;
        uint32_t sB = sA + 256u * 128u;
        const __nv_bfloat16* Ap = A + (size_t)kt * 64;
        const __nv_bfloat16* Bp = pb + (size_t)kt * 64;
#pragma unroll
        for (int i = 0; i < 8; i++) {
            int idx = tid + i * 256;
            int r = idx >> 3, c = idx & 7;
            CP_ASYNC(sA + (uint32_t)(r * 128 + ((c ^ (r & 7)) * 16)), Ap + (size_t)r * DEMB + c * 8);
        }
#pragma unroll
        for (int i = 0; i < 2; i++) {
            int idx = tid + i * 256;
            int r = idx >> 3, c = idx & 7;
            CP_ASYNC(sB + (uint32_t)(r * 128 + ((c ^ (r & 7)) * 16)), Bp + (size_t)r * DEMB + c * 8);
        }
        asm volatile("cp.async.commit_group;\n");
    };

    load(0);
    load(1);
    for (int kt = 0; kt < KT; kt++) {
        if (kt < KT - 1)
            asm volatile("cp.async.wait_group 1;\n" ::: "memory");
        else
            asm volatile("cp.async.wait_group 0;\n" ::: "memory");
        __syncthreads();
        if (kt + 2 < KT) load(kt + 2);
        uint32_t aBase = sbase + (kt % 3) * STP_STAGE;
        uint32_t bBase = aBase + 256u * 128u;
#pragma unroll
        for (int ks = 0; ks < 4; ks++) {
            uint32_t af[2][4];
#pragma unroll
            for (int mi = 0; mi < 2; mi++) {
                int row = wm + mi * 16 + (lane & 15);
                int ch = (ks * 2 + (lane >> 4)) ^ (row & 7);
                uint32_t adr = aBase + (uint32_t)(row * 128 + ch * 16);
                asm volatile("ldmatrix.sync.aligned.m8n8.x4.shared.b16 {%0,%1,%2,%3},[%4];"
                             : "=r"(af[mi][0]), "=r"(af[mi][1]), "=r"(af[mi][2]), "=r"(af[mi][3])
                             : "r"(adr));
            }
            uint32_t bfr[8][2];
#pragma unroll
            for (int ni2 = 0; ni2 < 4; ni2++) {
                int nrow = ni2 * 16 + (lane & 7) + ((lane >> 4) << 3);
                int ch = (ks * 2 + ((lane >> 3) & 1)) ^ (nrow & 7);
                uint32_t bd = bBase + (uint32_t)(nrow * 128 + ch * 16);
                uint32_t r0, r1, r2, r3;
                asm volatile("ldmatrix.sync.aligned.m8n8.x4.shared.b16 {%0,%1,%2,%3},[%4];"
                             : "=r"(r0), "=r"(r1), "=r"(r2), "=r"(r3)
                             : "r"(bd));
                bfr[2 * ni2][0] = r0; bfr[2 * ni2][1] = r1;
                bfr[2 * ni2 + 1][0] = r2; bfr[2 * ni2 + 1][1] = r3;
            }
#pragma unroll
            for (int mi = 0; mi < 2; mi++)
#pragma unroll
                for (int ni = 0; ni < 8; ni++)
                    asm volatile(
                        "mma.sync.aligned.m16n8k16.row.col.f32.bf16.bf16.f32 "
                        "{%0,%1,%2,%3},{%4,%5,%6,%7},{%8,%9},{%0,%1,%2,%3};"
                        : "+f"(acc[mi][ni][0]), "+f"(acc[mi][ni][1]),
                          "+f"(acc[mi][ni][2]), "+f"(acc[mi][ni][3])
                        : "r"(af[mi][0]), "r"(af[mi][1]), "r"(af[mi][2]), "r"(af[mi][3]),
                          "r"(bfr[ni][0]), "r"(bfr[ni][1]));
        }
    }

    // argmin over 64 classes (margin = pnorm - 2*dot), tie -> lowest index
    {
        float bv[2][2];
        int bc[2][2];
#pragma unroll
        for (int mi = 0; mi < 2; mi++)
#pragma unroll
            for (int h = 0; h < 2; h++) { bv[mi][h] = 1e30f; bc[mi][h] = 0; }
#pragma unroll
        for (int ni = 0; ni < 8; ni++)
#pragma unroll
            for (int j = 0; j < 2; j++) {
                int c = ni * 8 + (lane & 3) * 2 + j;
                float pn = __ldg(&pnorm[c]);
#pragma unroll
                for (int mi = 0; mi < 2; mi++)
#pragma unroll
                    for (int h = 0; h < 2; h++) {
                        float m = pn - 2.f * acc[mi][ni][2 * h + j];
                        if (m < bv[mi][h]) { bv[mi][h] = m; bc[mi][h] = c; }
                    }
            }
#pragma unroll
        for (int off = 1; off <= 2; off <<= 1)
#pragma unroll
            for (int mi = 0; mi < 2; mi++)
#pragma unroll
                for (int h = 0; h < 2; h++) {
                    float ov = __shfl_xor_sync(~0u, bv[mi][h], off);
                    int oc = __shfl_xor_sync(~0u, bc[mi][h], off);
                    if (ov < bv[mi][h] || (ov == bv[mi][h] && oc < bc[mi][h])) {
                        bv[mi][h] = ov; bc[mi][h] = oc;
                    }
                }
        if ((lane & 3) == 0) {
#pragma unroll
            for (int mi = 0; mi < 2; mi++)
#pragma unroll
                for (int h = 0; h < 2; h++) {
                    int row = wm + mi * 16 + (lane >> 2) + 8 * h;
                    labels_s[row] = (short)bc[mi][h];
                    atomicAdd(&hist[bc[mi][h]], 1);
                }
        }
    }
    __syncthreads();
    if (tid < NCLS) atomicAdd(&qcount[tid], (float)hist[tid]);

    // ---- Phase B: per-class accumulate of own 256 rows ----
    // bins[rg][cls][cp]: 4 row-groups x 64 classes x 64 float2 = 128KB
    float2* bins = (float2*)smem_raw;
    float4* bins4 = (float4*)smem_raw;   // [rg][cls][32 float4]
    const int rg = tid >> 6;        // 0..3 (rows rg*64 .. rg*64+63)
    const int cp = tid & 63;        // bf162 column within 64-pair chunk
    const __nv_bfloat162* q2 = (const __nv_bfloat162*)(qemb) + (size_t)bm0 * 512;
    // initial zero (flush re-zeroes between chunks)
    for (int i = tid; i < 4 * NCLS * 64; i += 256) {
        bins[i].x = 0.f; bins[i].y = 0.f;
    }
    __syncthreads();
#pragma unroll 1
    for (int chunk = 0; chunk < 8; chunk++) {
        float2* mybins = bins + rg * NCLS * 64 + cp;
#pragma unroll 4
        for (int r = 0; r < 64; r++) {
            int row = rg * 64 + r;
            int L = labels_s[row];
            float2 v = __bfloat1622float2(q2[(size_t)row * 512 + chunk * 64 + cp]);
            float2* b = mybins + L * 64;
            b->x += v.x; b->y += v.y;
        }
        __syncthreads();
        // flush: sum 4 row-groups, red.v4 to qsum, re-zero bins for next chunk
        const float4 z4 = make_float4(0.f, 0.f, 0.f, 0.f);
        for (int i = tid; i < NCLS * 32; i += 256) {
            int cls = i >> 5, c4 = i & 31;
            float4 s0 = bins4[(0 * NCLS + cls) * 32 + c4];
            float4 s1 = bins4[(1 * NCLS + cls) * 32 + c4];
            float4 s2 = bins4[(2 * NCLS + cls) * 32 + c4];
            float4 s3 = bins4[(3 * NCLS + cls) * 32 + c4];
            bins4[(0 * NCLS + cls) * 32 + c4] = z4;
            bins4[(1 * NCLS + cls) * 32 + c4] = z4;
            bins4[(2 * NCLS + cls) * 32 + c4] = z4;
            bins4[(3 * NCLS + cls) * 32 + c4] = z4;
            float4 v;
            v.x = s0.x + s1.x + s2.x + s3.x;
            v.y = s0.y + s1.y + s2.y + s3.y;
            v.z = s0.z + s1.z + s2.z + s3.z;
            v.w = s0.w + s1.w + s2.w + s3.w;
            RED_V4(&qsum[cls * DEMB + chunk * 128 + c4 * 4], v);
        }
        __syncthreads();
    }
}

// ---------------- bf16 HMMA GEMM (embedding + logits) ----------------
// MODE 0: merged embedding GEMM (query + support), bias fused, qnorm accumulated
// MODE 2: outf[m*NCLS+n] = -sqrt(max(qnorm[m]+pnorm[n]-2*C, 1e-12))
template <int BM, int BN, int WMT, int WNT, int MODE>
__global__ void __launch_bounds__(WMT* WNT * 32, 1) k_gemm(
    const __nv_bfloat16* __restrict__ A, const __nv_bfloat16* __restrict__ B, int K,
    const float* __restrict__ bias, __nv_bfloat16* __restrict__ outb, int ldo,
    const float* __restrict__ pnorm, float* __restrict__ qnorm, float* __restrict__ outf,
    const __nv_bfloat16* __restrict__ A2, __nv_bfloat16* __restrict__ outb2, int nqy) {
    constexpr int NT = WMT * WNT * 32;
    constexpr int WM = BM / WMT, WN = BN / WNT;
    constexpr int MF = WM / 16, NF = WN / 8;
    constexpr int AIT = BM * 8 / NT;
    constexpr int BIT = BN * 8 / NT;
    constexpr uint32_t STAGE = (BM + BN) * 128;

    extern __shared__ char smem_raw[];
    uint32_t sbase = (uint32_t)__cvta_generic_to_shared(smem_raw);

    const int tid = threadIdx.x;
    const int warp = tid >> 5, lane = tid & 31;
    const int wm = (warp / WNT) * WM, wn = (warp % WNT) * WN;
    const int bn0 = blockIdx.x * BN;

    bool isq = true;
    int ybase = blockIdx.y;
    const __nv_bfloat16* Asel = A;
    __nv_bfloat16* osel = outb;
    if (MODE == 0 && (int)blockIdx.y >= nqy) {
        isq = false;
        ybase = blockIdx.y - nqy;
        Asel = A2;
        osel = outb2;
    }
    const int bm0 = ybase * BM;

    const __nv_bfloat16* Ab = Asel + (size_t)bm0 * K;
    const __nv_bfloat16* Bb = B + (size_t)bn0 * K;

    float acc[MF][NF][4];
#pragma unroll
    for (int i = 0; i < MF; i++)
#pragma unroll
        for (int j = 0; j < NF; j++)
#pragma unroll
            for (int q = 0; q < 4; q++) acc[i][j][q] = 0.f;

    const int KT = K >> 6;

    auto load = [&](int kt) {
        uint32_t sA = sbase + (kt % 3) * STAGE;
        uint32_t sB = sA + (uint32_t)BM * 128u;
        const __nv_bfloat16* Ap = Ab + (size_t)kt * 64;
        const __nv_bfloat16* Bp = Bb + (size_t)kt * 64;
#pragma unroll
        for (int i = 0; i < AIT; i++) {
            int idx = tid + i * NT;
            int r = idx >> 3, c = idx & 7;
            CP_ASYNC(sA + (uint32_t)(r * 128 + ((c ^ (r & 7)) * 16)), Ap + (size_t)r * K + c * 8);
        }
#pragma unroll
        for (int i = 0; i < BIT; i++) {
            int idx = tid + i * NT;
            int r = idx >> 3, c = idx & 7;
            CP_ASYNC(sB + (uint32_t)(r * 128 + ((c ^ (r & 7)) * 16)), Bp + (size_t)r * K + c * 8);
        }
        asm volatile("cp.async.commit_group;\n");
    };

    load(0);
    load(1);
    for (int kt = 0; kt < KT; kt++) {
        if (kt < KT - 1)
            asm volatile("cp.async.wait_group 1;\n" ::: "memory");
        else
            asm volatile("cp.async.wait_group 0;\n" ::: "memory");
        __syncthreads();
        if (kt + 2 < KT) load(kt + 2);
        uint32_t aBase = sbase + (kt % 3) * STAGE;
        uint32_t bBase = aBase + (uint32_t)BM * 128u;
#pragma unroll
        for (int ks = 0; ks < 4; ks++) {
            uint32_t af[MF][4];
#pragma unroll
            for (int mi = 0; mi < MF; mi++) {
                int row = wm + mi * 16 + (lane & 15);
                int ch = (ks * 2 + (lane >> 4)) ^ (row & 7);
                uint32_t adr = aBase + (uint32_t)(row * 128 + ch * 16);
                asm volatile("ldmatrix.sync.aligned.m8n8.x4.shared.b16 {%0,%1,%2,%3},[%4];"
                             : "=r"(af[mi][0]), "=r"(af[mi][1]), "=r"(af[mi][2]), "=r"(af[mi][3])
                             : "r"(adr));
            }
            uint32_t bfr[NF][2];
#pragma unroll
            for (int ni2 = 0; ni2 < NF / 2; ni2++) {
                int nrow = wn + ni2 * 16 + (lane & 7) + ((lane >> 4) << 3);
                int ch = (ks * 2 + ((lane >> 3) & 1)) ^ (nrow & 7);
                uint32_t bd = bBase + (uint32_t)(nrow * 128 + ch * 16);
                uint32_t r0, r1, r2, r3;
                asm volatile("ldmatrix.sync.aligned.m8n8.x4.shared.b16 {%0,%1,%2,%3},[%4];"
                             : "=r"(r0), "=r"(r1), "=r"(r2), "=r"(r3)
                             : "r"(bd));
                bfr[2 * ni2][0] = r0; bfr[2 * ni2][1] = r1;
                bfr[2 * ni2 + 1][0] = r2; bfr[2 * ni2 + 1][1] = r3;
            }
#pragma unroll
            for (int mi = 0; mi < MF; mi++)
#pragma unroll
                for (int ni = 0; ni < NF; ni++)
                    asm volatile(
                        "mma.sync.aligned.m16n8k16.row.col.f32.bf16.bf16.f32 "
                        "{%0,%1,%2,%3},{%4,%5,%6,%7},{%8,%9},{%0,%1,%2,%3};"
                        : "+f"(acc[mi][ni][0]), "+f"(acc[mi][ni][1]),
                          "+f"(acc[mi][ni][2]), "+f"(acc[mi][ni][3])
                        : "r"(af[mi][0]), "r"(af[mi][1]), "r"(af[mi][2]), "r"(af[mi][3]),
                          "r"(bfr[ni][0]), "r"(bfr[ni][1]));
        }
    }

    if (MODE == 0) {
#pragma unroll
        for (int mi = 0; mi < MF; mi++) {
            int row = bm0 + wm + mi * 16 + (lane >> 2);
#pragma unroll
            for (int h = 0; h < 2; h++) {
                int rr = row + h * 8;
                float rs = 0.f;
#pragma unroll
                for (int ni = 0; ni < NF; ni++) {
                    int col = bn0 + wn + ni * 8 + (lane & 3) * 2;
                    float b0v = __ldg(&bias[col]), b1v = __ldg(&bias[col + 1]);
                    __nv_bfloat162 p = __floats2bfloat162_rn(acc[mi][ni][2 * h] + b0v,
                                                             acc[mi][ni][2 * h + 1] + b1v);
                    *(__nv_bfloat162*)(osel + (size_t)rr * ldo + col) = p;
                    float x = __bfloat162float(p.x), y = __bfloat162float(p.y);
                    rs += x * x + y * y;
                }
                if (isq) {
                    rs += __shfl_xor_sync(~0u, rs, 1);
                    rs += __shfl_xor_sync(~0u, rs, 2);
                    if ((lane & 3) == 0) atomicAdd(&qnorm[rr], rs);
                }
            }
        }
    } else {  // MODE 2
#pragma unroll
        for (int mi = 0; mi < MF; mi++) {
            int row = bm0 + wm + mi * 16 + (lane >> 2);
#pragma unroll
            for (int h = 0; h < 2; h++) {
                int rr = row + 8 * h;
                float qn = __ldg(&qnorm[rr]);
#pragma unroll
                for (int ni = 0; ni < NF; ni++)
#pragma unroll
                    for (int j = 0; j < 2; j++) {
                        int c = wn + ni * 8 + (lane & 3) * 2 + j;
                        float d2 = qn + __ldg(&pnorm[c]) - 2.f * acc[mi][ni][2 * h + j];
                        outf[(size_t)rr * NCLS + c] = -sqrtf(fmaxf(d2, 1e-12f));
                    }
            }
        }
    }
}

// ---------------- host orchestration ----------------
extern "C" void kernel_launch(void* const* d_in, const int* in_sizes, int n_in,
                              void* d_out, int out_size) {
    (void)in_sizes; (void)n_in; (void)out_size;
    const float* support = (const float*)d_in[0];
    const float* query = (const float*)d_in[1];
    const int* slab = (const int*)d_in[2];
    const float* W = (const float*)d_in[3];
    const float* bias = (const float*)d_in[4];
    float* out = (float*)d_out;

    __nv_bfloat16 *Wt, *qx, *sx, *qemb, *semb, *pb;
    float *qnorm, *ssum, *scount, *qsum, *qcount, *pnorm;
    cudaGetSymbolAddress((void**)&Wt, g_Wt);
    cudaGetSymbolAddress((void**)&qx, g_qx);
    cudaGetSymbolAddress((void**)&sx, g_sx);
    cudaGetSymbolAddress((void**)&qemb, g_qemb);
    cudaGetSymbolAddress((void**)&semb, g_semb);
    cudaGetSymbolAddress((void**)&qnorm, g_qnorm);
    cudaGetSymbolAddress((void**)&ssum, g_ssum);
    cudaGetSymbolAddress((void**)&scount, g_scount);
    cudaGetSymbolAddress((void**)&qsum, g_qsum);
    cudaGetSymbolAddress((void**)&qcount, g_qcount);
    cudaGetSymbolAddress((void**)&pb, g_pb);
    cudaGetSymbolAddress((void**)&pnorm, g_pnorm);

    const int SMEM_BIG = 3 * (128 + 256) * 128;   // 147456
    const int SMEM_SML = 3 * (128 + 64) * 128;    // 73728
    cudaFuncSetAttribute(k_gemm<128, 256, 2, 4, 0>, cudaFuncAttributeMaxDynamicSharedMemorySize, SMEM_BIG);
    cudaFuncSetAttribute(k_gemm<128, 64, 4, 2, 2>, cudaFuncAttributeMaxDynamicSharedMemorySize, SMEM_SML);
    cudaFuncSetAttribute(k_step, cudaFuncAttributeMaxDynamicSharedMemorySize, STP_SMEM);

    // launch order: profiler captures the 4th launch = merged big GEMM
    k_convert<<<(NQRY * DIN / 4 + 255) / 256, 256>>>(query, qx, NQRY * DIN / 4);
    k_convert<<<(NSUP * DIN / 4 + 255) / 256, 256>>>(support, sx, NSUP * DIN / 4);
    k_transpose_w<<<dim3(DEMB / 32, DIN / 32), dim3(32, 8)>>>(W, Wt, qnorm, ssum, scount);

    // merged embedding GEMM (query y-blocks [0,512), support [512,522))
    k_gemm<128, 256, 2, 4, 0><<<dim3(DEMB / 256, QYB + NSUP / 128), 256, SMEM_BIG>>>(
        qx, Wt, DIN, bias, qemb, DEMB, nullptr, qnorm, nullptr, sx, semb, QYB);

    // support class sums + counts -> initial prototypes (also zeroes qsum/qcount)
    k_supp_stats<<<NSUP, 256>>>(semb, slab, ssum, scount);
    k_proto<<<NCLS, 256>>>(ssum, scount, qsum, qcount, 0, pb, pnorm);

    for (int s = 0; s < NSTEPS; s++) {
        k_step<<<dim3(1, NQRY / 256), 256, STP_SMEM>>>(qemb, pb, pnorm, qsum, qcount);
        k_proto<<<NCLS, 256>>>(ssum, scount, qsum, qcount, 1, pb, pnorm);
    }

    // final logits
    k_gemm<128, 64, 4, 2, 2><<<dim3(1, NQRY / 128), 256, SMEM_SML>>>(
        qemb, pb, DEMB, nullptr, nullptr, 0, pnorm, qnorm, out, nullptr, nullptr, 1 << 20);
}